// round 5
// baseline (speedup 1.0000x reference)
#include <cuda_runtime.h>
#include <math.h>

// ---------------- constants matching the reference ----------------
#define HH 121
#define WW 121
#define NE 225
#define NB 8
#define NSPLIT 8
#define CHUNK 29                       // ceil(225/8)
#define N_INTERP 200
#define RET_PER_DVA 280.0f
#define XRANGE0 (-15.0f)
#define YRANGE0 (-15.0f)
#define XYSTEP 0.25f
#define XLOWc (-4200.0f)
#define YLOWc (-4200.0f)
#define STEP_Xc (8400.0f/199.0f)
#define STEP_Yc (8400.0f/199.0f)
#define OD_OFF_Xc (15.5f*280.0f)
#define AMP_CUTOFF 0.25f
#define PIc 3.14159265358979323846f
#define TEMP1c (4.0f*PIc)
#define NEG_HALF_LOG2E (-0.7213475204444817f)   // -0.5*log2(e)
#define LOG2_045 (-1.1520030934450498f)         // log2(0.45)

#define NPIX (HH*WW)
#define TILES_X 4
#define TILES_Y 8

// partial images per electrode-split
__device__ float g_part[NSPLIT * NB * NPIX];
// per-(b, tile) completion counters (statically zero; reset by finisher)
__device__ int   g_done[NB * TILES_X * TILES_Y];

__device__ __forceinline__ float ex2_fast(float x) {
    float r;
    asm("ex2.approx.ftz.f32 %0, %1;" : "=f"(r) : "f"(x));
    return r;
}

// grid (4, 8, NB*NSPLIT), block 128.
// Phase 1: warp 0 computes per-electrode params for this block's 29-electrode
//          chunk (single-warp ballot compaction).
// Phase 2: warp = 32 cols x 4 rows tile; finite-difference row evaluation.
// Phase 3: last split-block for this (b,tile) sums partials -> out.
__global__ __launch_bounds__(128, 12) void mvg_main_kernel(
        const float* __restrict__ stim,
        const float* __restrict__ params,
        const float* __restrict__ elec_x,
        const float* __restrict__ elec_y,
        const float* __restrict__ slopes,
        float* __restrict__ out) {
    __shared__ float4 sA[CHUNK];   // cx, cy2, -, bright
    __shared__ float4 sB[CHUNK];   // c00, c01, c11, 2*c11
    __shared__ int    s_len;
    __shared__ int    s_last;

    int bz = blockIdx.z;
    int b = bz >> 3;               // NSPLIT == 8
    int split = bz & 7;
    int e0 = split * CHUNK;
    int len = min(NE - e0, CHUNK);

    int tid = threadIdx.x;
    int lane = tid & 31, w = tid >> 5;

    // ---------------- phase 1: per-electrode precompute (warp 0) ----------------
    if (w == 0) {
        bool act = false;
        float cx = 0.f, cy2 = 0.f, bright = 0.f;
        float c00 = 0.f, c01 = 0.f, c11 = 0.f;

        if (lane < len) {
            int e = e0 + lane;
            const float* P = params + b * 13;
            float rho = P[0], lam = P[1], osc = P[2];
            float a0 = P[3], a1 = P[4], a2 = P[5], a3 = P[6], a4 = P[7];
            float impx = P[8], impy = P[9], rot = P[10], lodx = P[11];
            float cr = __cosf(rot), sr = __sinf(rot);

            float exv = elec_x[e] * cr - elec_y[e] * sr + impx;
            float eyv = elec_x[e] * sr + elec_y[e] * cr + impy;
            float freq = stim[(b * NE + e) * 3 + 0];
            float amp  = stim[(b * NE + e) * 3 + 1];
            float pdur = stim[(b * NE + e) * 3 + 2];

            if (amp > AMP_CUTOFF) {
                act = true;
                float offx = lodx - OD_OFF_Xc;
                float qx = (exv - offx - XLOWc) * (1.0f / STEP_Xc);
                float qy = (eyv - YLOWc) * (1.0f / STEP_Yc);

                float fx = fminf(fmaxf(floorf(qx), 0.f), (float)(N_INTERP - 2));
                float fy = fminf(fmaxf(floorf(qy), 0.f), (float)(N_INTERP - 2));
                int ix = (int)fx, iy = (int)fy;
                float ax = fminf(fmaxf(qx - fx, 0.f), 1.f);
                float ay = fminf(fmaxf(qy - fy, 0.f), 1.f);
                float g00 = slopes[iy * N_INTERP + ix];
                float g01 = slopes[iy * N_INTERP + ix + 1];
                float g10 = slopes[(iy + 1) * N_INTERP + ix];
                float g11 = slopes[(iy + 1) * N_INTERP + ix + 1];
                float top = g00 + ax * (g01 - g00);
                float bot = g10 + ax * (g11 - g10);
                float th = top + ay * (bot - top);
                if (th < -PIc * 0.5f) th += PIc;
                th *= osc;

                float rs = fmaxf(rho * amp * a3, 1.0f);
                // 0.45^-a4 * pdur^a4 = exp2(a4*(log2(pdur) - log2(0.45)))
                float ls = lam * ex2_fast(a4 * (__log2f(pdur) - LOG2_045));
                ls = fminf(fmaxf(ls, 0.f), 0.99f);
                bright = a0 * ex2_fast(a1 * __log2f(fmaxf(amp, 1e-5f))) + a2 * freq;

                float t2 = sqrtf(1.0f - ls * ls);
                float sy = __fdividef(rs, TEMP1c * t2);
                float sx = rs * t2 * (1.0f / TEMP1c);
                float s = __sinf(th), c = __cosf(th);
                float cov00 = sx * c * c + sy * s * s;
                float cov01 = (sx - sy) * s * c;
                float cov11 = sx * s * s + sy * c * c;
                float det = cov00 * cov11 - cov01 * cov01;
                float rdet = __fdividef(1.0f, det);
                float inv00 = cov11 * rdet;
                float inv01 = -cov01 * rdet;
                float inv11 = cov00 * rdet;

                c00 = NEG_HALF_LOG2E * inv00;
                c01 = 2.0f * NEG_HALF_LOG2E * inv01;
                c11 = NEG_HALF_LOG2E * inv11;

                cx = (exv / RET_PER_DVA - XRANGE0) / XYSTEP;
                float cy = (float)HH - (eyv / RET_PER_DVA - YRANGE0) / XYSTEP;
                cy2 = 120.0f - cy;   // d1 = cy2 - r
            }
        }

        // single-warp deterministic popc compaction (ascending e preserved)
        unsigned mask = __ballot_sync(0xffffffffu, act);
        if (lane == 0) s_len = __popc(mask);
        if (act) {
            int slot = __popc(mask & ((1u << lane) - 1u));
            sA[slot] = make_float4(cx, cy2, 0.f, bright);
            sB[slot] = make_float4(c00, c01, c11, 2.0f * c11);
        }
    }
    __syncthreads();
    int n = s_len;

    // ---------------- phase 2: pixel loop (finite differences over rows) ----
    int c  = blockIdx.x * 32 + lane;
    int r0 = blockIdx.y * 16 + w * 4;

    float cf  = (float)c;
    float rf0 = (float)r0;

    float acc0 = 0.f, acc1 = 0.f, acc2 = 0.f, acc3 = 0.f;

    for (int e = 0; e < n; e++) {
        float4 A = sA[e];                       // cx, cy2, -, bright
        float4 B = sB[e];                       // c00, c01, c11, 2*c11
        float d0 = cf - A.x;
        float k1 = B.y * d0;                    // c01*d0
        float k0 = (B.x * d0) * d0;             // c00*d0^2
        float d1 = A.y - rf0;

        // t(r0) and first difference; second difference = B.w = 2*c11
        float t   = fmaf(fmaf(B.z, d1, k1), d1, k0);
        float dlt = fmaf(B.z, fmaf(-2.0f, d1, 1.0f), -k1);

        acc0 = fmaf(A.w, ex2_fast(t), acc0);
        t += dlt; dlt += B.w;
        acc1 = fmaf(A.w, ex2_fast(t), acc1);
        t += dlt; dlt += B.w;
        acc2 = fmaf(A.w, ex2_fast(t), acc2);
        t += dlt;
        acc3 = fmaf(A.w, ex2_fast(t), acc3);
    }

    float* dst = g_part + (split * NB + b) * NPIX + c;
    if (c < WW) {
        if (r0 + 0 < HH) dst[(r0 + 0) * WW] = acc0;
        if (r0 + 1 < HH) dst[(r0 + 1) * WW] = acc1;
        if (r0 + 2 < HH) dst[(r0 + 2) * WW] = acc2;
        if (r0 + 3 < HH) dst[(r0 + 3) * WW] = acc3;
    }

    // ---------------- phase 3: last-block reduction ----------------
    __threadfence();
    __syncthreads();
    if (tid == 0) {
        int idx = (b * TILES_X + blockIdx.x) * TILES_Y + blockIdx.y;
        int old = atomicAdd(&g_done[idx], 1);
        s_last = (old == NSPLIT - 1) ? 1 : 0;
        if (s_last) g_done[idx] = 0;      // reset for next graph replay
    }
    __syncthreads();

    if (s_last) {
        int col0 = blockIdx.x * 32;
        int row0 = blockIdx.y * 16;
        for (int k = tid; k < 512; k += 128) {
            int r = row0 + (k >> 5);
            int cc = col0 + (k & 31);
            if (r < HH && cc < WW) {
                int p = r * WW + cc;
                // fixed split order -> deterministic fp sum
                float v = 0.f;
#pragma unroll
                for (int sp = 0; sp < NSPLIT; sp++)
                    v += __ldcg(&g_part[(sp * NB + b) * NPIX + p]);
                out[b * NPIX + p] = v;
            }
        }
    }
}

extern "C" void kernel_launch(void* const* d_in, const int* in_sizes, int n_in,
                              void* d_out, int out_size) {
    const float* stim   = (const float*)d_in[0];  // (8,225,3)
    const float* params = (const float*)d_in[1];  // (8,13)
    const float* ex     = (const float*)d_in[2];  // (1,225)
    const float* ey     = (const float*)d_in[3];  // (1,225)
    const float* slopes = (const float*)d_in[4];  // (200,200)
    // d_in[5] = pixelgrid: implied analytically, unused

    dim3 grid(TILES_X, TILES_Y, NB * NSPLIT);   // (4,8,64)
    mvg_main_kernel<<<grid, 128>>>(stim, params, ex, ey, slopes, (float*)d_out);
}